// round 9
// baseline (speedup 1.0000x reference)
#include <cuda_runtime.h>
#include <cuda_bf16.h>
#include <stdint.h>

// Problem constants
#define KDIM     1024
#define NROWS    8192
#define NCLASSES 50257
#define SHORTC   4000
#define BOUND1   20000
#define NVIRT    50259            // 50257 classes + 2 tail-cluster vectors
#define NPAD     50304            // 393 * 128 col tiles

// INT8 scaling: x*24, w*1024 -> logits scaled by 24576
#define ASCALE 24.0f
#define WSCALE 1024.0f
#define SINV   (1.0f / (ASCALE * WSCALE))

// GEMM tiling: 128x128 CTA tile, 2 CTAs/SM, int8 K-chunk = 128 elems = 128 B
#define BM   128
#define BN   128
#define BK   128                  // int8 per K chunk = 128 B/row = one SW128 atom
#define NCHUNK (KDIM / BK)        // 8
#define NSTAGE 3

// smem layout (bytes from dynamic base)
#define SM_BIAS   0               // 128 floats
#define SM_TILES  1024
#define STAGE_BYTES 32768         // A 16 KB + B 16 KB
#define SM_A(s)  (SM_TILES + (s) * STAGE_BYTES)
#define SM_B(s)  (SM_A(s) + 16384)
#define SMEM_BYTES (SM_TILES + NSTAGE * STAGE_BYTES)   // 99328 -> 2 CTAs/SM

// -------- scratch (device globals; no runtime allocation allowed) --------
__device__ uint8_t g_A[(size_t)NROWS * KDIM];           // 8 MB  int8 input  (x * 24)
__device__ uint8_t g_W[(size_t)NPAD * KDIM];            // 51 MB int8 weights (w * 1024)
__device__ float g_biasv[NPAD];
__device__ float g_sum[3 * NROWS];
__device__ float g_tl[NROWS];
__device__ float g_t1v[NROWS];
__device__ float g_t2v[NROWS];
__device__ float g_loss;

// ---------------- helpers ----------------
__device__ __forceinline__ uint32_t smem_u32(const void* p) {
    uint32_t a;
    asm("{ .reg .u64 t; cvta.to.shared.u64 t, %1; cvt.u32.u64 %0, t; }" : "=r"(a) : "l"(p));
    return a;
}
__device__ __forceinline__ void cp16(uint32_t dst, const void* src) {
    asm volatile("cp.async.cg.shared.global [%0], [%1], 16;\n" :: "r"(dst), "l"(src));
}
__device__ __forceinline__ void cp_commit() { asm volatile("cp.async.commit_group;\n"); }

__device__ __forceinline__ uint32_t swz(uint32_t off) {      // SW128 swizzle
    return off ^ ((off >> 3) & 0x70);
}

// quantize one float to s8 in [-127,127]
__device__ __forceinline__ int q8(float f, float s) {
    int v = __float2int_rn(f * s);
    v = max(-127, min(127, v));
    return v;
}
__device__ __forceinline__ uint32_t pack_s8x4(int a, int b, int c, int d) {
    return (uint32_t)(a & 0xFF) | ((uint32_t)(b & 0xFF) << 8)
         | ((uint32_t)(c & 0xFF) << 16) | ((uint32_t)(d & 0xFF) << 24);
}

__device__ __forceinline__ void ldsm_x4(uint32_t* r, uint32_t addr) {
    asm volatile("ldmatrix.sync.aligned.m8n8.x4.shared.b16 {%0,%1,%2,%3}, [%4];"
                 : "=r"(r[0]), "=r"(r[1]), "=r"(r[2]), "=r"(r[3]) : "r"(addr));
}

__device__ __forceinline__ void mma16832i(int* d, const uint32_t* a, uint32_t b0, uint32_t b1) {
    asm volatile(
        "mma.sync.aligned.m16n8k32.row.col.s32.s8.s8.s32 "
        "{%0,%1,%2,%3}, {%4,%5,%6,%7}, {%8,%9}, {%0,%1,%2,%3};\n"
        : "+r"(d[0]), "+r"(d[1]), "+r"(d[2]), "+r"(d[3])
        : "r"(a[0]), "r"(a[1]), "r"(a[2]), "r"(a[3]), "r"(b0), "r"(b1));
}

// ---------------- small kernels ----------------
__global__ void k_zero() {
    int i = blockIdx.x * blockDim.x + threadIdx.x;
    if (i < 3 * NROWS) g_sum[i] = 0.0f;
    if (i == 0) g_loss = 0.0f;
}

__global__ void k_convert_A(const float* __restrict__ in) {
    size_t i = ((size_t)blockIdx.x * blockDim.x + threadIdx.x) * 16;
    if (i >= (size_t)NROWS * KDIM) return;
    uint4 o;
    uint32_t* po = &o.x;
#pragma unroll
    for (int q = 0; q < 4; q++) {
        float4 f = *(const float4*)(in + i + q * 4);
        po[q] = pack_s8x4(q8(f.x, ASCALE), q8(f.y, ASCALE), q8(f.z, ASCALE), q8(f.w, ASCALE));
    }
    *(uint4*)(g_A + i) = o;
}

__global__ void k_convert_W(const float* __restrict__ w, const float* __restrict__ tv) {
    size_t i = ((size_t)blockIdx.x * blockDim.x + threadIdx.x) * 16;
    if (i >= (size_t)NPAD * KDIM) return;
    int j = (int)(i >> 10), kk = (int)(i & 1023);
    const float* src;
    if (j < NCLASSES)      src = w + i;
    else if (j < NVIRT)    src = tv + (size_t)(j - NCLASSES) * KDIM + kk;
    else {
        *(uint4*)(g_W + i) = make_uint4(0, 0, 0, 0);
        return;
    }
    uint4 o;
    uint32_t* po = &o.x;
#pragma unroll
    for (int q = 0; q < 4; q++) {
        float4 f = *(const float4*)(src + q * 4);
        po[q] = pack_s8x4(q8(f.x, WSCALE), q8(f.y, WSCALE), q8(f.z, WSCALE), q8(f.w, WSCALE));
    }
    *(uint4*)(g_W + i) = o;
}

__global__ void k_bias(const float* __restrict__ bias, const float* __restrict__ tb) {
    int i = blockIdx.x * blockDim.x + threadIdx.x;
    if (i < NPAD) {
        float v;
        if (i < NCLASSES)   v = bias[i];
        else if (i < NVIRT) v = tb[i - NCLASSES];
        else                v = -INFINITY;       // pad cols -> exp = 0
        g_biasv[i] = v;
    }
}

// ---------------- stage loader: cp.async 16B with SW128 swizzle ----------------
__device__ __forceinline__ void load_stage(uint32_t sA, uint32_t sB,
                                           const char* gAb, const char* gWb,
                                           int chunk, int tid) {
    const char* srcA = gAb + chunk * 128;       // 128 B per chunk per row
#pragma unroll
    for (int i = 0; i < 4; i++) {               // 128 rows * 8 x 16B
        int u = tid + i * 256;
        int row = u >> 3, kc = u & 7;
        uint32_t off = row * 128 + kc * 16;
        cp16(sA + swz(off), srcA + (size_t)row * KDIM + kc * 16);
    }
    const char* srcB = gWb + chunk * 128;
#pragma unroll
    for (int i = 0; i < 4; i++) {               // 128 rows
        int u = tid + i * 256;
        int row = u >> 3, kc = u & 7;
        uint32_t off = row * 128 + kc * 16;
        cp16(sB + swz(off), srcB + (size_t)row * KDIM + kc * 16);
    }
    cp_commit();
}

// ---------------- main fused INT8 GEMM + exp-reduce ----------------
__global__ void __launch_bounds__(256, 2)
k_gemm_exp() {
    extern __shared__ __align__(1024) char smem[];
    const uint32_t sb = smem_u32(smem);
    const int tid = threadIdx.x, wid = tid >> 5, lane = tid & 31;
    const int rowBase = blockIdx.x * BM;
    const int colBase = blockIdx.y * BN;

    const char* gAb = (const char*)g_A + (size_t)rowBase * KDIM;
    const char* gWb = (const char*)g_W + (size_t)colBase * KDIM;

    float* biasS = (float*)(smem + SM_BIAS);
    if (tid < BN) biasS[tid] = g_biasv[colBase + tid];

    // 4 (m) x 2 (n) warp grid; warp tile 32 x 64
    const int mBase = (wid & 3) * 32;
    const int nBase = (wid >> 2) * 64;

    // per-lane ldmatrix base offsets (tile-relative bytes, before swizzle)
    const uint32_t offA0 = (mBase + (lane & 15)) * 128 + (lane >> 4) * 16;
    const uint32_t offB0 = (nBase + (lane & 7) + ((lane >> 4) & 1) * 8) * 128
                         + ((lane >> 3) & 1) * 16;

    int acc[2][8][4];
#pragma unroll
    for (int mi = 0; mi < 2; mi++)
#pragma unroll
        for (int ni = 0; ni < 8; ni++)
#pragma unroll
            for (int e = 0; e < 4; e++) acc[mi][ni][e] = 0;

    // prologue: stages 0,1
    load_stage(sb + SM_A(0), sb + SM_B(0), gAb, gWb, 0, tid);
    load_stage(sb + SM_A(1), sb + SM_B(1), gAb, gWb, 1, tid);

    int buf = 0;
    for (int c = 0; c < NCHUNK; c++) {
        if (c == NCHUNK - 1) asm volatile("cp.async.wait_group 0;\n");
        else                 asm volatile("cp.async.wait_group 1;\n");
        __syncthreads();

        if (c + 2 < NCHUNK) {
            int nb = buf + 2; if (nb >= NSTAGE) nb -= NSTAGE;
            load_stage(sb + SM_A(nb), sb + SM_B(nb), gAb, gWb, c + 2, tid);
        }

        const uint32_t aBase = sb + SM_A(buf);
        const uint32_t bBase = sb + SM_B(buf);
#pragma unroll
        for (int ks = 0; ks < 4; ks++) {        // 4 k32 steps x 32 B
            uint32_t af[2][4], bf[4][4];
#pragma unroll
            for (int mi = 0; mi < 2; mi++)
                ldsm_x4(af[mi], aBase + swz(offA0 + mi * 2048 + ks * 32));
#pragma unroll
            for (int pr = 0; pr < 4; pr++)
                ldsm_x4(bf[pr], bBase + swz(offB0 + pr * 2048 + ks * 32));
#pragma unroll
            for (int mi = 0; mi < 2; mi++)
#pragma unroll
                for (int ni = 0; ni < 8; ni++)
                    mma16832i(acc[mi][ni], af[mi], bf[ni >> 1][(ni & 1) * 2],
                              bf[ni >> 1][(ni & 1) * 2 + 1]);
        }
        buf++; if (buf >= NSTAGE) buf = 0;
    }

    // epilogue: de-scale + bias + exp + per-row segment sums
    const int g = lane >> 2, c4 = lane & 3;
#pragma unroll
    for (int mi = 0; mi < 2; mi++) {
#pragma unroll
        for (int half = 0; half < 2; half++) {
            const int row = rowBase + mBase + mi * 16 + g + half * 8;
            float s0 = 0.0f, s1 = 0.0f, s2 = 0.0f;
#pragma unroll
            for (int ni = 0; ni < 8; ni++) {
                const int colLocal = nBase + ni * 8 + 2 * c4;
#pragma unroll
                for (int e = 0; e < 2; e++) {
                    const int jj = colBase + colLocal + e;
                    const float logit = (float)acc[mi][ni][half * 2 + e] * SINV
                                      + biasS[colLocal + e];
                    const float ex = __expf(logit);
                    if (jj < SHORTC || jj >= NCLASSES) s0 += ex;   // pads: ex==0
                    else if (jj < BOUND1)              s1 += ex;
                    else                               s2 += ex;
                }
            }
            s0 += __shfl_xor_sync(0xffffffff, s0, 1); s0 += __shfl_xor_sync(0xffffffff, s0, 2);
            s1 += __shfl_xor_sync(0xffffffff, s1, 1); s1 += __shfl_xor_sync(0xffffffff, s1, 2);
            s2 += __shfl_xor_sync(0xffffffff, s2, 1); s2 += __shfl_xor_sync(0xffffffff, s2, 2);
            if (c4 == 0) {
                if (s0 != 0.0f) atomicAdd(&g_sum[row],             s0);
                if (s1 != 0.0f) atomicAdd(&g_sum[NROWS + row],     s1);
                if (s2 != 0.0f) atomicAdd(&g_sum[2 * NROWS + row], s2);
            }
        }
    }
}

// ---------------- exact fp32 target & tail-cluster logits ----------------
__global__ void k_target_dot(const float* __restrict__ input, const int* __restrict__ target,
                             const float* __restrict__ weight, const float* __restrict__ bias,
                             const float* __restrict__ tv, const float* __restrict__ tb) {
    const int warp = threadIdx.x >> 5, lane = threadIdx.x & 31;
    const int row = blockIdx.x * 8 + warp;
    if (row >= NROWS) return;
    const float4* ip = (const float4*)(input + (size_t)row * KDIM);
    const int t = target[row];
    const float4* wp  = (const float4*)(weight + (size_t)t * KDIM);
    const float4* tp0 = (const float4*)(tv);
    const float4* tp1 = (const float4*)(tv + KDIM);
    float d0 = 0.0f, d1 = 0.0f, d2 = 0.0f;
#pragma unroll
    for (int i = 0; i < 8; i++) {
        float4 x = ip[lane + 32 * i];
        float4 w = wp[lane + 32 * i];
        float4 a = tp0[lane + 32 * i];
        float4 b = tp1[lane + 32 * i];
        d0 += x.x * w.x + x.y * w.y + x.z * w.z + x.w * w.w;
        d1 += x.x * a.x + x.y * a.y + x.z * a.z + x.w * a.w;
        d2 += x.x * b.x + x.y * b.y + x.z * b.z + x.w * b.w;
    }
#pragma unroll
    for (int m = 16; m > 0; m >>= 1) {
        d0 += __shfl_xor_sync(0xffffffff, d0, m);
        d1 += __shfl_xor_sync(0xffffffff, d1, m);
        d2 += __shfl_xor_sync(0xffffffff, d2, m);
    }
    if (lane == 0) {
        g_tl[row]  = d0 + bias[t];
        g_t1v[row] = d1 + tb[0];
        g_t2v[row] = d2 + tb[1];
    }
}

// ---------------- final combine + loss ----------------
__global__ void k_final(const int* __restrict__ target, float* __restrict__ out, int out_size) {
    const int n = blockIdx.x * blockDim.x + threadIdx.x;
    float v = 0.0f;
    if (n < NROWS) {
        const float lse0 = logf(g_sum[n]);
        const int t = target[n];
        float o;
        if (t < SHORTC)      o = g_tl[n] - lse0;
        else if (t < BOUND1) o = (g_t1v[n] - lse0) + (g_tl[n] - logf(g_sum[NROWS + n]));
        else                 o = (g_t2v[n] - lse0) + (g_tl[n] - logf(g_sum[2 * NROWS + n]));
        if (n < out_size) out[n] = o;
        v = -o;
    }
    __shared__ float red[256];
    red[threadIdx.x] = v;
    __syncthreads();
    for (int s = 128; s > 0; s >>= 1) {
        if (threadIdx.x < s) red[threadIdx.x] += red[threadIdx.x + s];
        __syncthreads();
    }
    if (threadIdx.x == 0) atomicAdd(&g_loss, red[0]);
}

__global__ void k_writeloss(float* __restrict__ out, int out_size) {
    const float loss = g_loss * (1.0f / NROWS);
    if (out_size >= NROWS + 1) out[NROWS] = loss;
    else if (out_size == 1)    out[0] = loss;
}

// ---------------- launch ----------------
extern "C" void kernel_launch(void* const* d_in, const int* in_sizes, int n_in,
                              void* d_out, int out_size) {
    const float* input  = (const float*)d_in[0];
    const int*   target = (const int*)d_in[1];
    const float* weight = (const float*)d_in[2];
    const float* bias   = (const float*)d_in[3];
    const float* tv     = (const float*)d_in[4];
    const float* tb     = (const float*)d_in[5];
    float* out = (float*)d_out;

    cudaFuncSetAttribute(k_gemm_exp, cudaFuncAttributeMaxDynamicSharedMemorySize, SMEM_BYTES);

    k_zero<<<(3 * NROWS + 255) / 256, 256>>>();
    k_convert_A<<<(NROWS * KDIM / 16 + 255) / 256, 256>>>(input);
    k_convert_W<<<((int)((size_t)NPAD * KDIM / 16) + 255) / 256, 256>>>(weight, tv);
    k_bias<<<(NPAD + 255) / 256, 256>>>(bias, tb);
    k_gemm_exp<<<dim3(NROWS / BM, NPAD / BN), 256, SMEM_BYTES>>>();
    k_target_dot<<<NROWS / 8, 256>>>(input, target, weight, bias, tv, tb);
    k_final<<<NROWS / 256, 256>>>(target, out, out_size);
    k_writeloss<<<1, 1>>>(out, out_size);
}

// round 10
// speedup vs baseline: 2.6559x; 2.6559x over previous
#include <cuda_runtime.h>
#include <cuda_bf16.h>
#include <stdint.h>

// Problem constants
#define KDIM     1024
#define NROWS    8192
#define NCLASSES 50257
#define SHORTC   4000
#define BOUND1   20000
#define NVIRT    50259            // 50257 classes + 2 tail-cluster vectors
#define NPAD     50304            // 393 * 128 col tiles

// GEMM tiling: 128x128 tiles, persistent CTAs, 2 CTAs/SM
#define BM   128
#define BN   128
#define NCHUNK   16               // K chunks of 64 bf16 (128 B) each
#define NSTAGE   3
#define NT_ROW   (NROWS / BM)     // 64
#define NT_COL   (NPAD / BN)      // 393
#define NTILES   (NT_ROW * NT_COL)

// smem layout (bytes from dynamic base)
#define STAGE_BYTES 32768         // A 16 KB + B 16 KB
#define SM_A(s)  ((s) * STAGE_BYTES)
#define SM_B(s)  (SM_A(s) + 16384)
#define SMEM_BYTES (NSTAGE * STAGE_BYTES)   // 98304 -> 2 CTAs/SM

// -------- scratch (device globals; no runtime allocation allowed) --------
__device__ __nv_bfloat16 g_A[(size_t)NROWS * KDIM];     // 16 MB
__device__ __nv_bfloat16 g_W[(size_t)NPAD * KDIM];      // 103 MB (+tails, +zero pad)
__device__ float g_biasv[NPAD];
__device__ float g_sum[3 * NROWS];
__device__ float g_tl[NROWS];
__device__ float g_t1v[NROWS];
__device__ float g_t2v[NROWS];
__device__ float g_loss;

// ---------------- helpers ----------------
__device__ __forceinline__ uint32_t smem_u32(const void* p) {
    uint32_t a;
    asm("{ .reg .u64 t; cvta.to.shared.u64 t, %1; cvt.u32.u64 %0, t; }" : "=r"(a) : "l"(p));
    return a;
}
__device__ __forceinline__ void cp16(uint32_t dst, const void* src) {
    asm volatile("cp.async.cg.shared.global [%0], [%1], 16;\n" :: "r"(dst), "l"(src));
}
__device__ __forceinline__ uint32_t swz(uint32_t off) {      // SW128 swizzle
    return off ^ ((off >> 3) & 0x70);
}
__device__ __forceinline__ uint32_t pack_bf16x2(float lo, float hi) {
    uint32_t r;
    asm("cvt.rn.bf16x2.f32 %0, %1, %2;" : "=r"(r) : "f"(hi), "f"(lo));
    return r;
}
__device__ __forceinline__ void ldsm_x4(uint32_t* r, uint32_t addr) {
    asm volatile("ldmatrix.sync.aligned.m8n8.x4.shared.b16 {%0,%1,%2,%3}, [%4];"
                 : "=r"(r[0]), "=r"(r[1]), "=r"(r[2]), "=r"(r[3]) : "r"(addr));
}
__device__ __forceinline__ void mma16816(float* d, const uint32_t* a, uint32_t b0, uint32_t b1) {
    asm volatile(
        "mma.sync.aligned.m16n8k16.row.col.f32.bf16.bf16.f32 "
        "{%0,%1,%2,%3}, {%4,%5,%6,%7}, {%8,%9}, {%0,%1,%2,%3};\n"
        : "+f"(d[0]), "+f"(d[1]), "+f"(d[2]), "+f"(d[3])
        : "r"(a[0]), "r"(a[1]), "r"(a[2]), "r"(a[3]), "r"(b0), "r"(b1));
}

// ---------------- small kernels ----------------
__global__ void k_zero() {
    int i = blockIdx.x * blockDim.x + threadIdx.x;
    if (i < 3 * NROWS) g_sum[i] = 0.0f;
    if (i == 0) g_loss = 0.0f;
}

__global__ void k_convert_A(const float* __restrict__ in) {
    size_t i = ((size_t)blockIdx.x * blockDim.x + threadIdx.x) * 8;
    if (i >= (size_t)NROWS * KDIM) return;
    float4 f0 = *(const float4*)(in + i);
    float4 f1 = *(const float4*)(in + i + 4);
    uint4 o;
    o.x = pack_bf16x2(f0.x, f0.y);
    o.y = pack_bf16x2(f0.z, f0.w);
    o.z = pack_bf16x2(f1.x, f1.y);
    o.w = pack_bf16x2(f1.z, f1.w);
    *(uint4*)(g_A + i) = o;
}

__global__ void k_convert_W(const float* __restrict__ w, const float* __restrict__ tv) {
    size_t i = ((size_t)blockIdx.x * blockDim.x + threadIdx.x) * 8;
    if (i >= (size_t)NPAD * KDIM) return;
    int j = (int)(i >> 10), kk = (int)(i & 1023);
    const float* src;
    if (j < NCLASSES)      src = w + i;
    else if (j < NVIRT)    src = tv + (size_t)(j - NCLASSES) * KDIM + kk;
    else {
        *(uint4*)(g_W + i) = make_uint4(0, 0, 0, 0);
        return;
    }
    float4 f0 = *(const float4*)(src);
    float4 f1 = *(const float4*)(src + 4);
    uint4 o;
    o.x = pack_bf16x2(f0.x, f0.y);
    o.y = pack_bf16x2(f0.z, f0.w);
    o.z = pack_bf16x2(f1.x, f1.y);
    o.w = pack_bf16x2(f1.z, f1.w);
    *(uint4*)(g_W + i) = o;
}

__global__ void k_bias(const float* __restrict__ bias, const float* __restrict__ tb) {
    int i = blockIdx.x * blockDim.x + threadIdx.x;
    if (i < NPAD) {
        float v;
        if (i < NCLASSES)   v = bias[i];
        else if (i < NVIRT) v = tb[i - NCLASSES];
        else                v = -INFINITY;       // pad cols -> exp = 0
        g_biasv[i] = v;
    }
}

// ---------------- persistent fused GEMM + exp-reduce ----------------
__global__ void __launch_bounds__(256, 2)
k_gemm_exp() {
    extern __shared__ __align__(1024) char smem[];
    const uint32_t sb = smem_u32(smem);
    const int tid = threadIdx.x, wid = tid >> 5, lane = tid & 31;
    const int nCTA = gridDim.x;

    // 4 (m) x 2 (n) warp grid; warp tile 32 x 64
    const int mBase = (wid & 3) * 32;
    const int nBase = (wid >> 2) * 64;
    const uint32_t offA0 = (mBase + (lane & 15)) * 128 + (lane >> 4) * 16;
    const uint32_t offB0 = (nBase + (lane & 7) + ((lane >> 4) & 1) * 8) * 128
                         + ((lane >> 3) & 1) * 16;
    const int g = lane >> 2, c4 = lane & 3;

    // ---- load cursor: streams (tile, chunk) pairs continuously ----
    int lt = blockIdx.x;                  // tile being loaded
    int lc = 0;                           // chunk within tile lt
    int lbuf = 0;                         // stage for next load
    const char* lA = (const char*)g_A + (size_t)(lt % NT_ROW) * BM * KDIM * 2;
    const char* lB = (const char*)g_W + (size_t)(lt / NT_ROW) * BN * KDIM * 2;

    // total chunks this CTA will process
    int myTiles = (lt < NTILES) ? ((NTILES - 1 - lt) / nCTA + 1) : 0;
    int chunksLeft = myTiles * NCHUNK;

    // issue_load: one stage fill from cursor position, then advance
    auto issue_load = [&]() {
        if (lt >= NTILES) return;
        const uint32_t sA = sb + SM_A(lbuf);
        const uint32_t sB = sb + SM_B(lbuf);
        const char* srcA = lA + lc * 128;
        const char* srcB = lB + lc * 128;
#pragma unroll
        for (int i = 0; i < 4; i++) {
            int u = tid + i * 256;
            int row = u >> 3, kc = u & 7;
            uint32_t off = row * 128 + kc * 16;
            cp16(sA + swz(off), srcA + (size_t)row * 2048 + kc * 16);
        }
#pragma unroll
        for (int i = 0; i < 4; i++) {
            int u = tid + i * 256;
            int row = u >> 3, kc = u & 7;
            uint32_t off = row * 128 + kc * 16;
            cp16(sB + swz(off), srcB + (size_t)row * 2048 + kc * 16);
        }
        asm volatile("cp.async.commit_group;\n");
        lbuf++; if (lbuf == NSTAGE) lbuf = 0;
        if (++lc == NCHUNK) {
            lc = 0;
            lt += nCTA;
            if (lt < NTILES) {
                lA = (const char*)g_A + (size_t)(lt % NT_ROW) * BM * KDIM * 2;
                lB = (const char*)g_W + (size_t)(lt / NT_ROW) * BN * KDIM * 2;
            }
        }
    };

    // prologue: fill 2 stages
    issue_load();
    issue_load();

    int buf = 0;
    for (int t = blockIdx.x; t < NTILES; t += nCTA) {
        const int rowBase = (t % NT_ROW) * BM;
        const int colBase = (t / NT_ROW) * BN;

        float acc[2][8][4];
#pragma unroll
        for (int mi = 0; mi < 2; mi++)
#pragma unroll
            for (int ni = 0; ni < 8; ni++)
#pragma unroll
                for (int e = 0; e < 4; e++) acc[mi][ni][e] = 0.0f;

        for (int c = 0; c < NCHUNK; c++) {
            if (chunksLeft <= 2) asm volatile("cp.async.wait_group 0;\n");
            else                 asm volatile("cp.async.wait_group 1;\n");
            __syncthreads();

            issue_load();       // streams ahead, possibly into next tile

            const uint32_t aBase = sb + SM_A(buf);
            const uint32_t bBase = sb + SM_B(buf);
#pragma unroll
            for (int ks = 0; ks < 4; ks++) {
                uint32_t af[2][4], bf[4][4];
#pragma unroll
                for (int mi = 0; mi < 2; mi++)
                    ldsm_x4(af[mi], aBase + swz(offA0 + mi * 2048 + ks * 32));
#pragma unroll
                for (int pr = 0; pr < 4; pr++)
                    ldsm_x4(bf[pr], bBase + swz(offB0 + pr * 2048 + ks * 32));
#pragma unroll
                for (int mi = 0; mi < 2; mi++)
#pragma unroll
                    for (int ni = 0; ni < 8; ni++)
                        mma16816(acc[mi][ni], af[mi], bf[ni >> 1][(ni & 1) * 2],
                                 bf[ni >> 1][(ni & 1) * 2 + 1]);
            }
            buf++; if (buf == NSTAGE) buf = 0;
            chunksLeft--;
        }

        // epilogue: bias via L2 (__ldg), exp, per-row segment sums.
        // Touches no stage smem -> no extra sync; loads for the next tile
        // continue draining in the background.
        float bcol[8][2];
#pragma unroll
        for (int ni = 0; ni < 8; ni++)
#pragma unroll
            for (int e = 0; e < 2; e++)
                bcol[ni][e] = __ldg(&g_biasv[colBase + nBase + ni * 8 + 2 * c4 + e]);

#pragma unroll
        for (int mi = 0; mi < 2; mi++) {
#pragma unroll
            for (int half = 0; half < 2; half++) {
                const int row = rowBase + mBase + mi * 16 + g + half * 8;
                float s0 = 0.0f, s1 = 0.0f, s2 = 0.0f;
#pragma unroll
                for (int ni = 0; ni < 8; ni++) {
#pragma unroll
                    for (int e = 0; e < 2; e++) {
                        const int jj = colBase + nBase + ni * 8 + 2 * c4 + e;
                        const float logit = acc[mi][ni][half * 2 + e] + bcol[ni][e];
                        const float ex = __expf(logit);
                        if (jj < SHORTC || jj >= NCLASSES) s0 += ex;   // pads: ex==0
                        else if (jj < BOUND1)              s1 += ex;
                        else                               s2 += ex;
                    }
                }
                s0 += __shfl_xor_sync(0xffffffff, s0, 1); s0 += __shfl_xor_sync(0xffffffff, s0, 2);
                s1 += __shfl_xor_sync(0xffffffff, s1, 1); s1 += __shfl_xor_sync(0xffffffff, s1, 2);
                s2 += __shfl_xor_sync(0xffffffff, s2, 1); s2 += __shfl_xor_sync(0xffffffff, s2, 2);
                if (c4 == 0) {
                    if (s0 != 0.0f) atomicAdd(&g_sum[row],             s0);
                    if (s1 != 0.0f) atomicAdd(&g_sum[NROWS + row],     s1);
                    if (s2 != 0.0f) atomicAdd(&g_sum[2 * NROWS + row], s2);
                }
            }
        }
    }
}

// ---------------- exact fp32 target & tail-cluster logits ----------------
__global__ void k_target_dot(const float* __restrict__ input, const int* __restrict__ target,
                             const float* __restrict__ weight, const float* __restrict__ bias,
                             const float* __restrict__ tv, const float* __restrict__ tb) {
    const int warp = threadIdx.x >> 5, lane = threadIdx.x & 31;
    const int row = blockIdx.x * 8 + warp;
    if (row >= NROWS) return;
    const float4* ip = (const float4*)(input + (size_t)row * KDIM);
    const int t = target[row];
    const float4* wp  = (const float4*)(weight + (size_t)t * KDIM);
    const float4* tp0 = (const float4*)(tv);
    const float4* tp1 = (const float4*)(tv + KDIM);
    float d0 = 0.0f, d1 = 0.0f, d2 = 0.0f;
#pragma unroll
    for (int i = 0; i < 8; i++) {
        float4 x = ip[lane + 32 * i];
        float4 w = wp[lane + 32 * i];
        float4 a = tp0[lane + 32 * i];
        float4 b = tp1[lane + 32 * i];
        d0 += x.x * w.x + x.y * w.y + x.z * w.z + x.w * w.w;
        d1 += x.x * a.x + x.y * a.y + x.z * a.z + x.w * a.w;
        d2 += x.x * b.x + x.y * b.y + x.z * b.z + x.w * b.w;
    }
#pragma unroll
    for (int m = 16; m > 0; m >>= 1) {
        d0 += __shfl_xor_sync(0xffffffff, d0, m);
        d1 += __shfl_xor_sync(0xffffffff, d1, m);
        d2 += __shfl_xor_sync(0xffffffff, d2, m);
    }
    if (lane == 0) {
        g_tl[row]  = d0 + bias[t];
        g_t1v[row] = d1 + tb[0];
        g_t2v[row] = d2 + tb[1];
    }
}

// ---------------- final combine + loss ----------------
__global__ void k_final(const int* __restrict__ target, float* __restrict__ out, int out_size) {
    const int n = blockIdx.x * blockDim.x + threadIdx.x;
    float v = 0.0f;
    if (n < NROWS) {
        const float lse0 = logf(g_sum[n]);
        const int t = target[n];
        float o;
        if (t < SHORTC)      o = g_tl[n] - lse0;
        else if (t < BOUND1) o = (g_t1v[n] - lse0) + (g_tl[n] - logf(g_sum[NROWS + n]));
        else                 o = (g_t2v[n] - lse0) + (g_tl[n] - logf(g_sum[2 * NROWS + n]));
        if (n < out_size) out[n] = o;
        v = -o;
    }
    __shared__ float red[256];
    red[threadIdx.x] = v;
    __syncthreads();
    for (int s = 128; s > 0; s >>= 1) {
        if (threadIdx.x < s) red[threadIdx.x] += red[threadIdx.x + s];
        __syncthreads();
    }
    if (threadIdx.x == 0) atomicAdd(&g_loss, red[0]);
}

__global__ void k_writeloss(float* __restrict__ out, int out_size) {
    const float loss = g_loss * (1.0f / NROWS);
    if (out_size >= NROWS + 1) out[NROWS] = loss;
    else if (out_size == 1)    out[0] = loss;
}

// ---------------- launch ----------------
extern "C" void kernel_launch(void* const* d_in, const int* in_sizes, int n_in,
                              void* d_out, int out_size) {
    const float* input  = (const float*)d_in[0];
    const int*   target = (const int*)d_in[1];
    const float* weight = (const float*)d_in[2];
    const float* bias   = (const float*)d_in[3];
    const float* tv     = (const float*)d_in[4];
    const float* tb     = (const float*)d_in[5];
    float* out = (float*)d_out;

    int sm = 148;
    cudaDeviceGetAttribute(&sm, cudaDevAttrMultiProcessorCount, 0);
    const int gemmGrid = 2 * sm;

    cudaFuncSetAttribute(k_gemm_exp, cudaFuncAttributeMaxDynamicSharedMemorySize, SMEM_BYTES);

    k_zero<<<(3 * NROWS + 255) / 256, 256>>>();
    k_convert_A<<<(NROWS * KDIM / 8 + 255) / 256, 256>>>(input);
    k_convert_W<<<((int)((size_t)NPAD * KDIM / 8) + 255) / 256, 256>>>(weight, tv);
    k_bias<<<(NPAD + 255) / 256, 256>>>(bias, tb);
    k_gemm_exp<<<gemmGrid, 256, SMEM_BYTES>>>();
    k_target_dot<<<NROWS / 8, 256>>>(input, target, weight, bias, tv, tb);
    k_final<<<NROWS / 256, 256>>>(target, out, out_size);
    k_writeloss<<<1, 1>>>(out, out_size);
}

// round 13
// speedup vs baseline: 2.9481x; 1.1100x over previous
#include <cuda_runtime.h>
#include <cuda_bf16.h>
#include <stdint.h>

// Problem constants
#define KDIM     1024
#define NROWS    8192
#define NCLASSES 50257
#define SHORTC   4000
#define BOUND1   20000
#define NVIRT    50259            // 50257 classes + 2 tail-cluster vectors
#define NPAD     50304            // 393 * 128 col tiles

// GEMM tiling: 128x128 CTA tile, 2 CTAs/SM
#define BM   128
#define BN   128
#define BK   64                   // bf16 per K chunk = 128 B/row = one SW128 atom
#define NCHUNK (KDIM / BK)        // 16
#define NSTAGE 3

// smem layout (bytes from dynamic base)
#define SM_BIAS   0               // 128 floats
#define SM_TILES  1024
#define STAGE_BYTES 32768         // A 16 KB + B 16 KB
#define SM_A(s)  (SM_TILES + (s) * STAGE_BYTES)
#define SM_B(s)  (SM_A(s) + 16384)
#define SMEM_BYTES (SM_TILES + NSTAGE * STAGE_BYTES)   // 99328 -> 2 CTAs/SM

// -------- scratch (device globals; no runtime allocation allowed) --------
__device__ __nv_bfloat16 g_A[(size_t)NROWS * KDIM];     // 16 MB
__device__ __nv_bfloat16 g_W[(size_t)NPAD * KDIM];      // 103 MB (+tails, +zero pad)
__device__ float g_biasv[NPAD];
__device__ float g_sum[3 * NROWS];
__device__ float g_tl[NROWS];
__device__ float g_t1v[NROWS];
__device__ float g_t2v[NROWS];
__device__ float g_loss;

// ---------------- helpers ----------------
__device__ __forceinline__ uint32_t smem_u32(const void* p) {
    uint32_t a;
    asm("{ .reg .u64 t; cvta.to.shared.u64 t, %1; cvt.u32.u64 %0, t; }" : "=r"(a) : "l"(p));
    return a;
}
__device__ __forceinline__ void cp16(uint32_t dst, const void* src) {
    asm volatile("cp.async.cg.shared.global [%0], [%1], 16;\n" :: "r"(dst), "l"(src));
}
__device__ __forceinline__ uint32_t swz(uint32_t off) {      // SW128 swizzle
    return off ^ ((off >> 3) & 0x70);
}
__device__ __forceinline__ uint32_t pack_bf16x2(float lo, float hi) {
    uint32_t r;
    asm("cvt.rn.bf16x2.f32 %0, %1, %2;" : "=r"(r) : "f"(hi), "f"(lo));
    return r;
}
__device__ __forceinline__ void ldsm_x4(uint32_t* r, uint32_t addr) {
    asm volatile("ldmatrix.sync.aligned.m8n8.x4.shared.b16 {%0,%1,%2,%3}, [%4];"
                 : "=r"(r[0]), "=r"(r[1]), "=r"(r[2]), "=r"(r[3]) : "r"(addr));
}
__device__ __forceinline__ void mma16816(float* d, const uint32_t* a, uint32_t b0, uint32_t b1) {
    asm volatile(
        "mma.sync.aligned.m16n8k16.row.col.f32.bf16.bf16.f32 "
        "{%0,%1,%2,%3}, {%4,%5,%6,%7}, {%8,%9}, {%0,%1,%2,%3};\n"
        : "+f"(d[0]), "+f"(d[1]), "+f"(d[2]), "+f"(d[3])
        : "r"(a[0]), "r"(a[1]), "r"(a[2]), "r"(a[3]), "r"(b0), "r"(b1));
}

// ---------------- small kernels ----------------
__global__ void k_convert_A(const float* __restrict__ in) {
    size_t i = ((size_t)blockIdx.x * blockDim.x + threadIdx.x) * 8;
    if (i >= (size_t)NROWS * KDIM) return;
    float4 f0 = *(const float4*)(in + i);
    float4 f1 = *(const float4*)(in + i + 4);
    uint4 o;
    o.x = pack_bf16x2(f0.x, f0.y);
    o.y = pack_bf16x2(f0.z, f0.w);
    o.z = pack_bf16x2(f1.x, f1.y);
    o.w = pack_bf16x2(f1.z, f1.w);
    *(uint4*)(g_A + i) = o;
}

__global__ void k_convert_W(const float* __restrict__ w, const float* __restrict__ tv) {
    size_t i = ((size_t)blockIdx.x * blockDim.x + threadIdx.x) * 8;
    if (i >= (size_t)NPAD * KDIM) return;
    int j = (int)(i >> 10), kk = (int)(i & 1023);
    const float* src;
    if (j < NCLASSES)      src = w + i;
    else if (j < NVIRT)    src = tv + (size_t)(j - NCLASSES) * KDIM + kk;
    else {
        *(uint4*)(g_W + i) = make_uint4(0, 0, 0, 0);
        return;
    }
    float4 f0 = *(const float4*)(src);
    float4 f1 = *(const float4*)(src + 4);
    uint4 o;
    o.x = pack_bf16x2(f0.x, f0.y);
    o.y = pack_bf16x2(f0.z, f0.w);
    o.z = pack_bf16x2(f1.x, f1.y);
    o.w = pack_bf16x2(f1.z, f1.w);
    *(uint4*)(g_W + i) = o;
}

// bias setup + zero sums + zero loss, one launch
__global__ void k_bias_zero(const float* __restrict__ bias, const float* __restrict__ tb) {
    int i = blockIdx.x * blockDim.x + threadIdx.x;
    if (i < NPAD) {
        float v;
        if (i < NCLASSES)   v = bias[i];
        else if (i < NVIRT) v = tb[i - NCLASSES];
        else                v = -INFINITY;       // pad cols -> exp = 0
        g_biasv[i] = v;
    }
    if (i < 3 * NROWS) g_sum[i] = 0.0f;
    if (i == 0) g_loss = 0.0f;
}

// ---------------- stage loader: cp.async 16B with SW128 swizzle ----------------
__device__ __forceinline__ void load_stage(uint32_t sA, uint32_t sB,
                                           const char* gAb, const char* gWb,
                                           int chunk, int tid) {
    const char* srcA = gAb + chunk * 128;
#pragma unroll
    for (int i = 0; i < 4; i++) {               // 128 rows * 8 x 16B
        int u = tid + i * 256;
        int row = u >> 3, kc = u & 7;
        uint32_t off = row * 128 + kc * 16;
        cp16(sA + swz(off), srcA + (size_t)row * 2048 + kc * 16);
    }
    const char* srcB = gWb + chunk * 128;
#pragma unroll
    for (int i = 0; i < 4; i++) {               // 128 rows
        int u = tid + i * 256;
        int row = u >> 3, kc = u & 7;
        uint32_t off = row * 128 + kc * 16;
        cp16(sB + swz(off), srcB + (size_t)row * 2048 + kc * 16);
    }
    asm volatile("cp.async.commit_group;\n");
}

// ---------------- main fused GEMM + exp-reduce ----------------
__global__ void __launch_bounds__(256, 2)
k_gemm_exp() {
    extern __shared__ __align__(1024) char smem[];
    const uint32_t sb = smem_u32(smem);
    const int tid = threadIdx.x, wid = tid >> 5, lane = tid & 31;
    const int rowBase = blockIdx.x * BM;
    const int colBase = blockIdx.y * BN;

    const char* gAb = (const char*)g_A + (size_t)rowBase * KDIM * 2;
    const char* gWb = (const char*)g_W + (size_t)colBase * KDIM * 2;

    float* biasS = (float*)(smem + SM_BIAS);
    if (tid < BN) biasS[tid] = g_biasv[colBase + tid];

    // 4 (m) x 2 (n) warp grid; warp tile 32 x 64
    const int mBase = (wid & 3) * 32;
    const int nBase = (wid >> 2) * 64;

    // per-lane ldmatrix base offsets (tile-relative, before swizzle)
    const uint32_t offA0 = (mBase + (lane & 15)) * 128 + (lane >> 4) * 16;
    const uint32_t offB0 = (nBase + (lane & 7) + ((lane >> 4) & 1) * 8) * 128
                         + ((lane >> 3) & 1) * 16;

    float acc[2][8][4];
#pragma unroll
    for (int mi = 0; mi < 2; mi++)
#pragma unroll
        for (int ni = 0; ni < 8; ni++)
#pragma unroll
            for (int e = 0; e < 4; e++) acc[mi][ni][e] = 0.0f;

    // prologue: stages 0,1
    load_stage(sb + SM_A(0), sb + SM_B(0), gAb, gWb, 0, tid);
    load_stage(sb + SM_A(1), sb + SM_B(1), gAb, gWb, 1, tid);

    // fully-unrolled mainloop: buf/wait/addresses are compile-time per iteration
#pragma unroll
    for (int c = 0; c < NCHUNK; c++) {
        const int buf = c % NSTAGE;
        if (c == NCHUNK - 1) asm volatile("cp.async.wait_group 0;\n");
        else                 asm volatile("cp.async.wait_group 1;\n");
        __syncthreads();

        if (c + 2 < NCHUNK) {
            const int nb = (c + 2) % NSTAGE;
            load_stage(sb + SM_A(nb), sb + SM_B(nb), gAb, gWb, c + 2, tid);
        }

        const uint32_t aBase = sb + SM_A(buf);
        const uint32_t bBase = sb + SM_B(buf);
#pragma unroll
        for (int ks = 0; ks < 4; ks++) {
            uint32_t af[2][4], bf[4][4];
#pragma unroll
            for (int mi = 0; mi < 2; mi++)
                ldsm_x4(af[mi], aBase + swz(offA0 + mi * 2048 + ks * 32));
#pragma unroll
            for (int pr = 0; pr < 4; pr++)
                ldsm_x4(bf[pr], bBase + swz(offB0 + pr * 2048 + ks * 32));
#pragma unroll
            for (int mi = 0; mi < 2; mi++)
#pragma unroll
                for (int ni = 0; ni < 8; ni++)
                    mma16816(acc[mi][ni], af[mi], bf[ni >> 1][(ni & 1) * 2],
                             bf[ni >> 1][(ni & 1) * 2 + 1]);
        }
    }

    // epilogue: bias + exp + per-row segment sums
    const int g = lane >> 2, c4 = lane & 3;
#pragma unroll
    for (int mi = 0; mi < 2; mi++) {
#pragma unroll
        for (int half = 0; half < 2; half++) {
            const int row = rowBase + mBase + mi * 16 + g + half * 8;
            float s0 = 0.0f, s1 = 0.0f, s2 = 0.0f;
#pragma unroll
            for (int ni = 0; ni < 8; ni++) {
                const int colLocal = nBase + ni * 8 + 2 * c4;
#pragma unroll
                for (int e = 0; e < 2; e++) {
                    const int jj = colBase + colLocal + e;
                    const float logit = acc[mi][ni][half * 2 + e] + biasS[colLocal + e];
                    const float ex = __expf(logit);
                    if (jj < SHORTC || jj >= NCLASSES) s0 += ex;   // pads: ex==0
                    else if (jj < BOUND1)              s1 += ex;
                    else                               s2 += ex;
                }
            }
            s0 += __shfl_xor_sync(0xffffffff, s0, 1); s0 += __shfl_xor_sync(0xffffffff, s0, 2);
            s1 += __shfl_xor_sync(0xffffffff, s1, 1); s1 += __shfl_xor_sync(0xffffffff, s1, 2);
            s2 += __shfl_xor_sync(0xffffffff, s2, 1); s2 += __shfl_xor_sync(0xffffffff, s2, 2);
            if (c4 == 0) {
                if (s0 != 0.0f) atomicAdd(&g_sum[row],             s0);
                if (s1 != 0.0f) atomicAdd(&g_sum[NROWS + row],     s1);
                if (s2 != 0.0f) atomicAdd(&g_sum[2 * NROWS + row], s2);
            }
        }
    }
}

// ---------------- exact fp32 target & tail-cluster logits ----------------
__global__ void k_target_dot(const float* __restrict__ input, const int* __restrict__ target,
                             const float* __restrict__ weight, const float* __restrict__ bias,
                             const float* __restrict__ tv, const float* __restrict__ tb) {
    const int warp = threadIdx.x >> 5, lane = threadIdx.x & 31;
    const int row = blockIdx.x * 8 + warp;
    if (row >= NROWS) return;
    const float4* ip = (const float4*)(input + (size_t)row * KDIM);
    const int t = target[row];
    const float4* wp  = (const float4*)(weight + (size_t)t * KDIM);
    const float4* tp0 = (const float4*)(tv);
    const float4* tp1 = (const float4*)(tv + KDIM);
    float d0 = 0.0f, d1 = 0.0f, d2 = 0.0f;
#pragma unroll
    for (int i = 0; i < 8; i++) {
        float4 x = ip[lane + 32 * i];
        float4 w = wp[lane + 32 * i];
        float4 a = tp0[lane + 32 * i];
        float4 b = tp1[lane + 32 * i];
        d0 += x.x * w.x + x.y * w.y + x.z * w.z + x.w * w.w;
        d1 += x.x * a.x + x.y * a.y + x.z * a.z + x.w * a.w;
        d2 += x.x * b.x + x.y * b.y + x.z * b.z + x.w * b.w;
    }
#pragma unroll
    for (int m = 16; m > 0; m >>= 1) {
        d0 += __shfl_xor_sync(0xffffffff, d0, m);
        d1 += __shfl_xor_sync(0xffffffff, d1, m);
        d2 += __shfl_xor_sync(0xffffffff, d2, m);
    }
    if (lane == 0) {
        g_tl[row]  = d0 + bias[t];
        g_t1v[row] = d1 + tb[0];
        g_t2v[row] = d2 + tb[1];
    }
}

// ---------------- final combine + loss ----------------
__global__ void k_final(const int* __restrict__ target, float* __restrict__ out, int out_size) {
    const int n = blockIdx.x * blockDim.x + threadIdx.x;
    float v = 0.0f;
    if (n < NROWS) {
        const float lse0 = logf(g_sum[n]);
        const int t = target[n];
        float o;
        if (t < SHORTC)      o = g_tl[n] - lse0;
        else if (t < BOUND1) o = (g_t1v[n] - lse0) + (g_tl[n] - logf(g_sum[NROWS + n]));
        else                 o = (g_t2v[n] - lse0) + (g_tl[n] - logf(g_sum[2 * NROWS + n]));
        if (n < out_size) out[n] = o;
        v = -o;
    }
    __shared__ float red[256];
    red[threadIdx.x] = v;
    __syncthreads();
    for (int s = 128; s > 0; s >>= 1) {
        if (threadIdx.x < s) red[threadIdx.x] += red[threadIdx.x + s];
        __syncthreads();
    }
    if (threadIdx.x == 0) atomicAdd(&g_loss, red[0]);
}

__global__ void k_writeloss(float* __restrict__ out, int out_size) {
    const float loss = g_loss * (1.0f / NROWS);
    if (out_size >= NROWS + 1) out[NROWS] = loss;
    else if (out_size == 1)    out[0] = loss;
}

// ---------------- launch ----------------
extern "C" void kernel_launch(void* const* d_in, const int* in_sizes, int n_in,
                              void* d_out, int out_size) {
    const float* input  = (const float*)d_in[0];
    const int*   target = (const int*)d_in[1];
    const float* weight = (const float*)d_in[2];
    const float* bias   = (const float*)d_in[3];
    const float* tv     = (const float*)d_in[4];
    const float* tb     = (const float*)d_in[5];
    float* out = (float*)d_out;

    cudaFuncSetAttribute(k_gemm_exp, cudaFuncAttributeMaxDynamicSharedMemorySize, SMEM_BYTES);

    k_convert_A<<<(NROWS * KDIM / 8 + 255) / 256, 256>>>(input);
    k_convert_W<<<((int)((size_t)NPAD * KDIM / 8) + 255) / 256, 256>>>(weight, tv);
    k_bias_zero<<<(NPAD + 255) / 256, 256>>>(bias, tb);
    k_gemm_exp<<<dim3(NROWS / BM, NPAD / BN), 256, SMEM_BYTES>>>();
    k_target_dot<<<NROWS / 8, 256>>>(input, target, weight, bias, tv, tb);
    k_final<<<NROWS / 256, 256>>>(target, out, out_size);
    k_writeloss<<<1, 1>>>(out, out_size);
}